// round 15
// baseline (speedup 1.0000x reference)
#include <cuda_runtime.h>
#include <cuda_fp16.h>
#include <cstdint>

#define NB 4096     // anchors
#define ND 256      // dim
#define NL 4        // eps levels
#define NC 2048     // centroids per level
#define NN 100000   // labels per level
#define NFLAT (NL*NC)   // 8192 flat centroids
#define NT 2048         // total 128x128 tiles (32 m-tiles x 64 n-tiles)
#define NWORK 296       // persistent CTAs = 148 SMs x 2

// ---------------- device scratch (allocation-free) ----------------
__device__ __half g_an_h[NB * ND];       // normalized anchors, fp16   (2 MB)
__device__ __half g_c_h[NFLAT * ND];     // normalized centroids, fp16 (4 MB)
__device__ unsigned g_imx[NB];   // order-encoded float: max over non-pos
__device__ unsigned g_imn[NB];   // order-encoded float: min over pos
__device__ unsigned g_ctr;       // completion counter

// order-preserving float<->uint encoding (monotonic for all finite floats)
__device__ __forceinline__ unsigned fenc(float f) {
    unsigned u = __float_as_uint(f);
    return (u & 0x80000000u) ? ~u : (u | 0x80000000u);
}
__device__ __forceinline__ float fdec(unsigned k) {
    unsigned u = (k & 0x80000000u) ? (k ^ 0x80000000u) : ~k;
    return __uint_as_float(u);
}

__device__ __forceinline__ uint32_t smem_u32(const void* p) {
    uint32_t a;
    asm("{ .reg .u64 t; cvta.to.shared.u64 t, %1; cvt.u32.u64 %0, t; }" : "=r"(a) : "l"(p));
    return a;
}

// ldmatrix x4 (b16, non-transposed)
#define LDSM4(f, addr) \
    asm volatile("ldmatrix.sync.aligned.m8n8.x4.shared.b16 {%0,%1,%2,%3}, [%4];" \
        : "=r"((f)[0]), "=r"((f)[1]), "=r"((f)[2]), "=r"((f)[3]) : "r"(addr))

// mma m16n8k16 fp16 -> fp32
#define MMA16816(d, a, b0, b1) \
    asm volatile("mma.sync.aligned.m16n8k16.row.col.f32.f16.f16.f32 " \
        "{%0,%1,%2,%3},{%4,%5,%6,%7},{%8,%9},{%0,%1,%2,%3};" \
        : "+f"((d)[0]), "+f"((d)[1]), "+f"((d)[2]), "+f"((d)[3]) \
        : "r"((a)[0]), "r"((a)[1]), "r"((a)[2]), "r"((a)[3]), "r"(b0), "r"(b1))

#define CP_ASYNC16(sa, gp) \
    asm volatile("cp.async.cg.shared.global [%0], [%1], 16;" :: "r"(sa), "l"(gp))
#define CP_COMMIT() asm volatile("cp.async.commit_group;" ::: "memory")
#define CP_WAIT1()  asm volatile("cp.async.wait_group 1;"  ::: "memory")
#define CP_WAIT0()  asm volatile("cp.async.wait_group 0;"  ::: "memory")

// ---------------------------------------------------------------------------
// Fused prep: normalize anchors AND centroids -> fp16. One warp per row.
// Rows [0, NB) = anchors, rows [NB, NB+NFLAT) = centroids.
// Also inits atomic extrema and the completion counter (graph-replay safe).
// ---------------------------------------------------------------------------
__global__ void prep_kernel(const float* __restrict__ anchors,
                            const float* __restrict__ centroids) {
    int row  = blockIdx.x * 8 + (threadIdx.x >> 5);
    int lane = threadIdx.x & 31;

    const float* in;
    __half* oh;
    size_t  r;
    if (row < NB) { in = anchors;   oh = g_an_h; r = row; }
    else          { in = centroids; oh = g_c_h;  r = row - NB; }

    const float4* ip = reinterpret_cast<const float4*>(in) + r * (ND / 4);
    float4 v0 = ip[lane];
    float4 v1 = ip[lane + 32];
    float ss = v0.x*v0.x + v0.y*v0.y + v0.z*v0.z + v0.w*v0.w
             + v1.x*v1.x + v1.y*v1.y + v1.z*v1.z + v1.w*v1.w;
    #pragma unroll
    for (int o = 16; o > 0; o >>= 1) ss += __shfl_xor_sync(0xffffffffu, ss, o);
    float scale = 1.0f / fmaxf(sqrtf(ss), 1e-12f);

    size_t base = r * ND;
    __half2* oh2 = reinterpret_cast<__half2*>(oh + base);
    oh2[lane * 2]          = __floats2half2_rn(v0.x * scale, v0.y * scale);
    oh2[lane * 2 + 1]      = __floats2half2_rn(v0.z * scale, v0.w * scale);
    oh2[64 + lane * 2]     = __floats2half2_rn(v1.x * scale, v1.y * scale);
    oh2[64 + lane * 2 + 1] = __floats2half2_rn(v1.z * scale, v1.w * scale);

    if (row < NB && lane == 0) {
        g_imx[row] = fenc(-2.f);
        g_imn[row] = fenc( 2.f);
        if (row == 0) g_ctr = 0u;
    }
}

// ---------------------------------------------------------------------------
// Persistent fp16 HMMA GEMM (fp32 acc). 296 CTAs; CTA bid processes tiles
// bid, bid+296, ... (deterministic). The champion R8 mainloop is kept, but
// the "issue chunk kc+2" slots at kc=2/3 load the NEXT tile's chunks 0/1
// (continuous cross-tile chunk stream; stage parity identical), and next
// tile's labels load into double-buffered smem during kc=3. One pipeline
// fill per CTA instead of one per tile/wave.
// CTA tile 128x128, 8 warps in 2(M) x 4(N), warp tile 64x32, K chunks of 64.
// ---------------------------------------------------------------------------
#define TK 64
#define NKC 4
#define LDS 72                          // padded row stride (halves) — bank-clean
#define ARR_ELEMS (128*LDS)             // 9216 halves per array
#define STAGE_BYTES (2*ARR_ELEMS*2)     // A + B = 36864 B
#define TILES_BYTES (2*STAGE_BYTES)     // 73728
#define SMEM_TOTAL (TILES_BYTES + 1024 + 1024 + 2048 + 2048)

__global__ void __launch_bounds__(256, 2)
gemm_kernel(const int* __restrict__ clab,
            const int* __restrict__ lpe,
            const int* __restrict__ lidx,
            float* __restrict__ out) {
    extern __shared__ char smem[];
    int*   labA  = reinterpret_cast<int*>(smem + TILES_BYTES);        // [2][128]
    int*   labC  = labA + 256;                                        // [2][128]
    float* redmx = reinterpret_cast<float*>(labC + 256);              // 512
    float* redmn = redmx + 512;                                       // 512

    const int tid    = threadIdx.x;
    const int lane   = tid & 31;
    const int wid    = tid >> 5;
    const int warp_m = wid >> 2;          // 0..1
    const int warp_n = wid & 3;           // 0..3
    const int bid    = blockIdx.x;

    const uint32_t sb = smem_u32(smem);

    // tile t -> (m0, n0): mi fastest (matches old grid ordering for L2 reuse)
    auto load_labels = [&](int t, int p) {
        int mm0 = (t & 31) << 7;
        int nn0 = (t >> 5) << 7;
        int ll  = nn0 >> 11;
        if (tid < 128) labA[p * 128 + tid] = lpe[ll * NN + lidx[mm0 + tid]];
        else           labC[p * 128 + tid - 128] = clab[nn0 + tid - 128];
    };

    // per-thread cp.async slots: 8 x 16B per chunk (same mapping as champion)
    auto load_chunk = [&](int s, int t, int kc) {
        int mm0 = (t & 31) << 7;
        int nn0 = (t >> 5) << 7;
        const __half* gA = g_an_h + (size_t)mm0 * ND;
        const __half* gB = g_c_h  + (size_t)nn0 * ND;
        uint32_t stage = sb + s * STAGE_BYTES;
        #pragma unroll
        for (int i = 0; i < 8; i++) {
            int slot = tid + i * 256;
            int arr  = slot >> 10;
            int q    = slot & 1023;
            int r    = q >> 3, g = q & 7;
            const __half* src = (arr ? gB : gA) + (size_t)r * ND + kc * TK + g * 8;
            uint32_t sa = stage + 2u * (arr * ARR_ELEMS + r * LDS + g * 8);
            CP_ASYNC16(sa, src);
        }
        CP_COMMIT();
    };

    // ldmatrix lane addressing (A: m16 x k16; B: n16 x k16, k-contiguous)
    const int arow  = lane & 15;
    const int acol8 = (lane >> 4) * 8;
    const int brow  = (lane & 7) + ((lane >> 4) << 3);
    const int bcol8 = ((lane >> 3) & 1) * 8;

    // ---- one-time prologue: fill pipeline for first tile ----
    load_labels(bid, 0);
    load_chunk(0, bid, 0);
    load_chunk(1, bid, 1);

    int p = 0;
    for (int ti = bid; ti < NT; ti += NWORK, p ^= 1) {
        const bool has_next_tile = (ti + NWORK < NT);
        const int  m0 = (ti & 31) << 7;

        float acc[4][4][4];
        #pragma unroll
        for (int mt = 0; mt < 4; mt++)
            #pragma unroll
            for (int nt = 0; nt < 4; nt++)
                #pragma unroll
                for (int e = 0; e < 4; e++) acc[mt][nt][e] = 0.f;

        #pragma unroll
        for (int kc = 0; kc < NKC; kc++) {
            if (kc == NKC - 1 && !has_next_tile) CP_WAIT0(); else CP_WAIT1();
            __syncthreads();

            const uint32_t stage = sb + (kc & 1) * STAGE_BYTES;
            #pragma unroll
            for (int ks = 0; ks < 4; ks++) {
                const int k0 = ks * 16;
                uint32_t af[4][4], bh[2][4];

                #pragma unroll
                for (int bt = 0; bt < 2; bt++)
                    LDSM4(bh[bt], stage + 2u * (ARR_ELEMS + (warp_n * 32 + bt * 16 + brow) * LDS + k0 + bcol8));
                #pragma unroll
                for (int mt = 0; mt < 4; mt++)
                    LDSM4(af[mt], stage + 2u * ((warp_m * 64 + mt * 16 + arow) * LDS + k0 + acol8));

                #pragma unroll
                for (int mt = 0; mt < 4; mt++)
                    #pragma unroll
                    for (int bt = 0; bt < 2; bt++)
                        #pragma unroll
                        for (int j = 0; j < 2; j++)
                            MMA16816(acc[mt][bt * 2 + j], af[mt], bh[bt][j * 2], bh[bt][j * 2 + 1]);
            }
            __syncthreads();   // all warps done reading this stage

            // continuous chunk stream: kc<2 -> this tile's kc+2;
            // kc>=2 -> next tile's chunk kc-2 (same stage parity).
            if (kc < 2) {
                load_chunk(kc & 1, ti, kc + 2);
            } else if (has_next_tile) {
                load_chunk(kc & 1, ti + NWORK, kc - 2);
                if (kc == 3) load_labels(ti + NWORK, p ^ 1);  // other buffer
            }
        }

        // ---- epilogue: masked max/min from register fragments ----
        const int* lA = labA + p * 128;
        const int* lC = labC + p * 128;
        int collab[4][2], rowlab[4][2];
        #pragma unroll
        for (int nt = 0; nt < 4; nt++) {
            collab[nt][0] = lC[warp_n * 32 + nt * 8 + (lane & 3) * 2];
            collab[nt][1] = lC[warp_n * 32 + nt * 8 + (lane & 3) * 2 + 1];
        }
        #pragma unroll
        for (int mt = 0; mt < 4; mt++) {
            rowlab[mt][0] = lA[warp_m * 64 + mt * 16 + (lane >> 2)];
            rowlab[mt][1] = lA[warp_m * 64 + mt * 16 + (lane >> 2) + 8];
        }

        #pragma unroll
        for (int mt = 0; mt < 4; mt++) {
            #pragma unroll
            for (int h = 0; h < 2; h++) {
                int rl = rowlab[mt][h];
                float mx = -2.f, mn = 2.f;
                #pragma unroll
                for (int nt = 0; nt < 4; nt++) {
                    #pragma unroll
                    for (int cp = 0; cp < 2; cp++) {
                        float s = acc[mt][nt][h * 2 + cp];
                        bool isp = (rl >= 0) && (rl == collab[nt][cp]);
                        if (isp) mn = fminf(mn, s);
                        else     mx = fmaxf(mx, s);
                    }
                }
                #pragma unroll
                for (int o = 1; o <= 2; o <<= 1) {
                    mx = fmaxf(mx, __shfl_xor_sync(0xffffffffu, mx, o));
                    mn = fminf(mn, __shfl_xor_sync(0xffffffffu, mn, o));
                }
                if ((lane & 3) == 0) {
                    int rloc = warp_m * 64 + mt * 16 + (lane >> 2) + h * 8;
                    redmx[warp_n * 128 + rloc] = mx;
                    redmn[warp_n * 128 + rloc] = mn;
                }
            }
        }
        __syncthreads();

        if (tid < 128) {
            float mx = redmx[tid], mn = redmn[tid];
            #pragma unroll
            for (int w = 1; w < 4; w++) {
                mx = fmaxf(mx, redmx[w * 128 + tid]);
                mn = fminf(mn, redmn[w * 128 + tid]);
            }
            atomicMax(&g_imx[m0 + tid], fenc(mx));
            atomicMin(&g_imn[m0 + tid], fenc(mn));
        }
        // next tile's first mainloop barrier orders redmx/label reuse
    }

    // ---- last-CTA scalar reduction (no separate launch) ----
    __shared__ unsigned s_rank;
    __threadfence();                         // publish our atomics
    __syncthreads();                         // all atomics in this CTA issued
    if (tid == 0) s_rank = atomicAdd(&g_ctr, 1u);
    __syncthreads();
    if (s_rank != NWORK - 1) return;

    __threadfence();                         // acquire: see all CTAs' extrema
    float sum = 0.f, cnt = 0.f;
    const uint4* pmx = reinterpret_cast<const uint4*>(g_imx);
    const uint4* pmn = reinterpret_cast<const uint4*>(g_imn);
    for (int q = tid; q < NB / 4; q += 256) {
        uint4 ux = __ldcg(&pmx[q]);
        uint4 un = __ldcg(&pmn[q]);
        unsigned xs[4] = {ux.x, ux.y, ux.z, ux.w};
        unsigned ns[4] = {un.x, un.y, un.z, un.w};
        #pragma unroll
        for (int j = 0; j < 4; j++) {
            float mx = fdec(xs[j]);
            float mn = fdec(ns[j]);
            if (mn < 1.5f) {                 // has_pos; has_neg always true
                sum += fmaxf(mx - mn + 0.2f, 0.f);
                cnt += 1.f;
            }
        }
    }
    #pragma unroll
    for (int o = 16; o > 0; o >>= 1) {
        sum += __shfl_xor_sync(0xffffffffu, sum, o);
        cnt += __shfl_xor_sync(0xffffffffu, cnt, o);
    }
    if (lane == 0) { redmx[wid] = sum; redmn[wid] = cnt; }
    __syncthreads();
    if (tid == 0) {
        sum = 0.f; cnt = 0.f;
        #pragma unroll
        for (int w = 0; w < 8; w++) { sum += redmx[w]; cnt += redmn[w]; }
        out[0] = sum / fmaxf(cnt, 1.f);
    }
}

// ---------------------------------------------------------------------------
extern "C" void kernel_launch(void* const* d_in, const int* in_sizes, int n_in,
                              void* d_out, int out_size) {
    const float* anchors   = (const float*)d_in[0];   // [B, D]
    const float* centroids = (const float*)d_in[1];   // [L, C, D]
    const int*   clab      = (const int*)d_in[2];     // [L, C]
    const int*   lpe       = (const int*)d_in[3];     // [L, N]
    const int*   lidx      = (const int*)d_in[4];     // [B]

    cudaFuncSetAttribute(gemm_kernel, cudaFuncAttributeMaxDynamicSharedMemorySize, SMEM_TOTAL);

    prep_kernel<<<(NB + NFLAT) / 8, 256>>>(anchors, centroids);

    gemm_kernel<<<NWORK, 256, SMEM_TOTAL>>>(clab, lpe, lidx, (float*)d_out);
}

// round 16
// speedup vs baseline: 1.0324x; 1.0324x over previous
#include <cuda_runtime.h>
#include <cuda_fp16.h>
#include <cstdint>

#define NB 4096     // anchors
#define ND 256      // dim
#define NL 4        // eps levels
#define NC 2048     // centroids per level
#define NN 100000   // labels per level
#define NFLAT (NL*NC)   // 8192 flat centroids
#define NTILES 64       // 8192 / 128 N-tiles
#define GEMM_BLOCKS ((NB/128)*NTILES)   // 2048

// ---------------- device scratch (allocation-free) ----------------
__device__ __half g_an_h[NB * ND];       // normalized anchors, fp16   (2 MB)
__device__ __half g_c_h[NFLAT * ND];     // normalized centroids, fp16 (4 MB)
__device__ unsigned g_imx[NB];   // order-encoded float: max over non-pos
__device__ unsigned g_imn[NB];   // order-encoded float: min over pos
__device__ unsigned g_ctr;       // gemm completion counter

// order-preserving float<->uint encoding (monotonic for all finite floats)
__device__ __forceinline__ unsigned fenc(float f) {
    unsigned u = __float_as_uint(f);
    return (u & 0x80000000u) ? ~u : (u | 0x80000000u);
}
__device__ __forceinline__ float fdec(unsigned k) {
    unsigned u = (k & 0x80000000u) ? (k ^ 0x80000000u) : ~k;
    return __uint_as_float(u);
}

__device__ __forceinline__ uint32_t smem_u32(const void* p) {
    uint32_t a;
    asm("{ .reg .u64 t; cvta.to.shared.u64 t, %1; cvt.u32.u64 %0, t; }" : "=r"(a) : "l"(p));
    return a;
}

// ldmatrix x4 (b16, non-transposed)
#define LDSM4(f, addr) \
    asm volatile("ldmatrix.sync.aligned.m8n8.x4.shared.b16 {%0,%1,%2,%3}, [%4];" \
        : "=r"((f)[0]), "=r"((f)[1]), "=r"((f)[2]), "=r"((f)[3]) : "r"(addr))

// mma m16n8k16 fp16 -> fp32
#define MMA16816(d, a, b0, b1) \
    asm volatile("mma.sync.aligned.m16n8k16.row.col.f32.f16.f16.f32 " \
        "{%0,%1,%2,%3},{%4,%5,%6,%7},{%8,%9},{%0,%1,%2,%3};" \
        : "+f"((d)[0]), "+f"((d)[1]), "+f"((d)[2]), "+f"((d)[3]) \
        : "r"((a)[0]), "r"((a)[1]), "r"((a)[2]), "r"((a)[3]), "r"(b0), "r"(b1))

#define CP_ASYNC16(sa, gp) \
    asm volatile("cp.async.cg.shared.global [%0], [%1], 16;" :: "r"(sa), "l"(gp))
#define CP_COMMIT() asm volatile("cp.async.commit_group;" ::: "memory")
#define CP_WAIT1()  asm volatile("cp.async.wait_group 1;"  ::: "memory")
#define CP_WAIT0()  asm volatile("cp.async.wait_group 0;"  ::: "memory")

// ---------------------------------------------------------------------------
// Fused prep: normalize anchors AND centroids -> fp16. One warp per row.
// Rows [0, NB) = anchors, rows [NB, NB+NFLAT) = centroids.
// Also inits atomic extrema and the completion counter (graph-replay safe).
// ---------------------------------------------------------------------------
__global__ void prep_kernel(const float* __restrict__ anchors,
                            const float* __restrict__ centroids) {
    int row  = blockIdx.x * 8 + (threadIdx.x >> 5);
    int lane = threadIdx.x & 31;

    const float* in;
    __half* oh;
    size_t  r;
    if (row < NB) { in = anchors;   oh = g_an_h; r = row; }
    else          { in = centroids; oh = g_c_h;  r = row - NB; }

    const float4* ip = reinterpret_cast<const float4*>(in) + r * (ND / 4);
    float4 v0 = ip[lane];
    float4 v1 = ip[lane + 32];
    float ss = v0.x*v0.x + v0.y*v0.y + v0.z*v0.z + v0.w*v0.w
             + v1.x*v1.x + v1.y*v1.y + v1.z*v1.z + v1.w*v1.w;
    #pragma unroll
    for (int o = 16; o > 0; o >>= 1) ss += __shfl_xor_sync(0xffffffffu, ss, o);
    float scale = 1.0f / fmaxf(sqrtf(ss), 1e-12f);

    size_t base = r * ND;
    // coalesced half2 stores
    __half2* oh2 = reinterpret_cast<__half2*>(oh + base);
    oh2[lane * 2]          = __floats2half2_rn(v0.x * scale, v0.y * scale);
    oh2[lane * 2 + 1]      = __floats2half2_rn(v0.z * scale, v0.w * scale);
    oh2[64 + lane * 2]     = __floats2half2_rn(v1.x * scale, v1.y * scale);
    oh2[64 + lane * 2 + 1] = __floats2half2_rn(v1.z * scale, v1.w * scale);

    if (row < NB && lane == 0) {
        g_imx[row] = fenc(-2.f);
        g_imn[row] = fenc( 2.f);
        if (row == 0) g_ctr = 0u;
    }
}

// ---------------------------------------------------------------------------
// Single-pass fp16 HMMA GEMM (fp32 acc) — champion configuration (final).
// CTA tile 128x128, 8 warps in 2(M) x 4(N), warp tile 64x32.
// K = 256 in 4 chunks of 64, 2-stage cp.async pipeline, padded smem stride.
// Masked max/min epilogue -> global atomics; last block reduces to scalar.
// Measured at 98.3% of the sm_103a legacy-mma MAC ceiling (~512 MACs/cyc/SM);
// invariant under pipeline depth, smem layout, occupancy, and persistence
// (rounds 8-15). tcgen05 path unavailable from the harness's compute_103 PTX.
// ---------------------------------------------------------------------------
#define TK 64
#define NKC 4
#define LDS 72                          // padded row stride (halves) — bank-clean
#define ARR_ELEMS (128*LDS)             // 9216 halves per array
#define STAGE_BYTES (2*ARR_ELEMS*2)     // A + B = 36864 B
#define TILES_BYTES (2*STAGE_BYTES)     // 73728
#define SMEM_TOTAL (TILES_BYTES + 512 + 512 + 2048 + 2048)

__global__ void __launch_bounds__(256, 2)
gemm_kernel(const int* __restrict__ clab,
            const int* __restrict__ lpe,
            const int* __restrict__ lidx,
            float* __restrict__ out) {
    extern __shared__ char smem[];
    int*   labA  = reinterpret_cast<int*>(smem + TILES_BYTES);
    int*   labC  = labA + 128;
    float* redmx = reinterpret_cast<float*>(labC + 128);
    float* redmn = redmx + 512;

    const int tid    = threadIdx.x;
    const int lane   = tid & 31;
    const int wid    = tid >> 5;
    const int warp_m = wid >> 2;          // 0..1
    const int warp_n = wid & 3;           // 0..3
    const int m0     = blockIdx.x * 128;
    const int n0     = blockIdx.y * 128;
    const int l      = n0 >> 11;          // tile fully within one eps level

    if (tid < 128) labA[tid] = lpe[l * NN + lidx[m0 + tid]];
    else           labC[tid - 128] = clab[n0 + tid - 128];

    const __half* gA = g_an_h + (size_t)m0 * ND;
    const __half* gB = g_c_h  + (size_t)n0 * ND;

    const uint32_t sb = smem_u32(smem);

    // per-thread cp.async slots: 8 x 16B per chunk.
    // slot = tid + i*256 in [0,2048): arr = slot>>10; q = slot&1023;
    // r = q>>3 (0..127); g = q&7 (64 halves = 8 x 16B groups)
    auto load_chunk = [&](int s, int kc) {
        uint32_t stage = sb + s * STAGE_BYTES;
        #pragma unroll
        for (int i = 0; i < 8; i++) {
            int slot = tid + i * 256;
            int arr  = slot >> 10;
            int q    = slot & 1023;
            int r    = q >> 3, g = q & 7;
            const __half* src = (arr ? gB : gA) + (size_t)r * ND + kc * TK + g * 8;
            uint32_t sa = stage + 2u * (arr * ARR_ELEMS + r * LDS + g * 8);
            CP_ASYNC16(sa, src);
        }
    };

    float acc[4][4][4];
    #pragma unroll
    for (int mt = 0; mt < 4; mt++)
        #pragma unroll
        for (int nt = 0; nt < 4; nt++)
            #pragma unroll
            for (int e = 0; e < 4; e++) acc[mt][nt][e] = 0.f;

    // ldmatrix lane addressing (A: m16 x k16; B: n16 x k16, k-contiguous)
    const int arow  = lane & 15;
    const int acol8 = (lane >> 4) * 8;
    const int brow  = (lane & 7) + ((lane >> 4) << 3);
    const int bcol8 = ((lane >> 3) & 1) * 8;

    load_chunk(0, 0); CP_COMMIT();
    load_chunk(1, 1); CP_COMMIT();

    for (int kc = 0; kc < NKC; kc++) {
        if (kc < NKC - 1) CP_WAIT1(); else CP_WAIT0();
        __syncthreads();

        const uint32_t stage = sb + (kc & 1) * STAGE_BYTES;
        #pragma unroll
        for (int ks = 0; ks < 4; ks++) {
            const int k0 = ks * 16;
            uint32_t af[4][4], bh[2][4];

            #pragma unroll
            for (int bt = 0; bt < 2; bt++)
                LDSM4(bh[bt], stage + 2u * (ARR_ELEMS + (warp_n * 32 + bt * 16 + brow) * LDS + k0 + bcol8));
            #pragma unroll
            for (int mt = 0; mt < 4; mt++)
                LDSM4(af[mt], stage + 2u * ((warp_m * 64 + mt * 16 + arow) * LDS + k0 + acol8));

            #pragma unroll
            for (int mt = 0; mt < 4; mt++)
                #pragma unroll
                for (int bt = 0; bt < 2; bt++)
                    #pragma unroll
                    for (int j = 0; j < 2; j++)
                        MMA16816(acc[mt][bt * 2 + j], af[mt], bh[bt][j * 2], bh[bt][j * 2 + 1]);
        }
        __syncthreads();   // all warps done reading this stage

        if (kc + 2 < NKC) { load_chunk(kc & 1, kc + 2); CP_COMMIT(); }
    }

    // ---- epilogue: masked max/min from register fragments ----
    // fragment: d[h*2+cp] at row = lane/4 + h*8, col = (lane&3)*2 + cp
    int collab[4][2], rowlab[4][2];
    #pragma unroll
    for (int nt = 0; nt < 4; nt++) {
        collab[nt][0] = labC[warp_n * 32 + nt * 8 + (lane & 3) * 2];
        collab[nt][1] = labC[warp_n * 32 + nt * 8 + (lane & 3) * 2 + 1];
    }
    #pragma unroll
    for (int mt = 0; mt < 4; mt++) {
        rowlab[mt][0] = labA[warp_m * 64 + mt * 16 + (lane >> 2)];
        rowlab[mt][1] = labA[warp_m * 64 + mt * 16 + (lane >> 2) + 8];
    }

    #pragma unroll
    for (int mt = 0; mt < 4; mt++) {
        #pragma unroll
        for (int h = 0; h < 2; h++) {
            int rl = rowlab[mt][h];
            float mx = -2.f, mn = 2.f;
            #pragma unroll
            for (int nt = 0; nt < 4; nt++) {
                #pragma unroll
                for (int cp = 0; cp < 2; cp++) {
                    float s = acc[mt][nt][h * 2 + cp];
                    bool isp = (rl >= 0) && (rl == collab[nt][cp]);
                    if (isp) mn = fminf(mn, s);
                    else     mx = fmaxf(mx, s);
                }
            }
            #pragma unroll
            for (int o = 1; o <= 2; o <<= 1) {
                mx = fmaxf(mx, __shfl_xor_sync(0xffffffffu, mx, o));
                mn = fminf(mn, __shfl_xor_sync(0xffffffffu, mn, o));
            }
            if ((lane & 3) == 0) {
                int rloc = warp_m * 64 + mt * 16 + (lane >> 2) + h * 8;
                redmx[warp_n * 128 + rloc] = mx;
                redmn[warp_n * 128 + rloc] = mn;
            }
        }
    }
    __syncthreads();

    if (tid < 128) {
        float mx = redmx[tid], mn = redmn[tid];
        #pragma unroll
        for (int w = 1; w < 4; w++) {
            mx = fmaxf(mx, redmx[w * 128 + tid]);
            mn = fminf(mn, redmn[w * 128 + tid]);
        }
        atomicMax(&g_imx[m0 + tid], fenc(mx));
        atomicMin(&g_imn[m0 + tid], fenc(mn));
    }

    // ---- last-block scalar reduction (no separate launch) ----
    __shared__ unsigned s_rank;
    __threadfence();                         // publish our atomics
    __syncthreads();                         // all atomics in this block issued
    if (tid == 0) s_rank = atomicAdd(&g_ctr, 1u);
    __syncthreads();
    if (s_rank != GEMM_BLOCKS - 1) return;

    __threadfence();                         // acquire: see all blocks' extrema
    float sum = 0.f, cnt = 0.f;
    const uint4* pmx = reinterpret_cast<const uint4*>(g_imx);
    const uint4* pmn = reinterpret_cast<const uint4*>(g_imn);
    for (int q = tid; q < NB / 4; q += 256) {
        uint4 ux = __ldcg(&pmx[q]);
        uint4 un = __ldcg(&pmn[q]);
        unsigned xs[4] = {ux.x, ux.y, ux.z, ux.w};
        unsigned ns[4] = {un.x, un.y, un.z, un.w};
        #pragma unroll
        for (int j = 0; j < 4; j++) {
            float mx = fdec(xs[j]);
            float mn = fdec(ns[j]);
            if (mn < 1.5f) {                 // has_pos; has_neg always true
                sum += fmaxf(mx - mn + 0.2f, 0.f);
                cnt += 1.f;
            }
        }
    }
    #pragma unroll
    for (int o = 16; o > 0; o >>= 1) {
        sum += __shfl_xor_sync(0xffffffffu, sum, o);
        cnt += __shfl_xor_sync(0xffffffffu, cnt, o);
    }
    if (lane == 0) { redmx[wid] = sum; redmn[wid] = cnt; }
    __syncthreads();
    if (tid == 0) {
        sum = 0.f; cnt = 0.f;
        #pragma unroll
        for (int w = 0; w < 8; w++) { sum += redmx[w]; cnt += redmn[w]; }
        out[0] = sum / fmaxf(cnt, 1.f);
    }
}

// ---------------------------------------------------------------------------
extern "C" void kernel_launch(void* const* d_in, const int* in_sizes, int n_in,
                              void* d_out, int out_size) {
    const float* anchors   = (const float*)d_in[0];   // [B, D]
    const float* centroids = (const float*)d_in[1];   // [L, C, D]
    const int*   clab      = (const int*)d_in[2];     // [L, C]
    const int*   lpe       = (const int*)d_in[3];     // [L, N]
    const int*   lidx      = (const int*)d_in[4];     // [B]

    cudaFuncSetAttribute(gemm_kernel, cudaFuncAttributeMaxDynamicSharedMemorySize, SMEM_TOTAL);

    prep_kernel<<<(NB + NFLAT) / 8, 256>>>(anchors, centroids);

    dim3 grid(NB / 128, NTILES);
    gemm_kernel<<<grid, 256, SMEM_TOTAL>>>(clab, lpe, lidx, (float*)d_out);
}